// round 3
// baseline (speedup 1.0000x reference)
#include <cuda_runtime.h>
#include <cstdint>
#include <cstddef>

// ============================ problem constants ============================
#define BATCH_N   4096
#define KDIM      512
#define CLS       50000
#define SCALE_F   30.0f
#define LMAX_F    30.0f
#define COSM_F    0.8775825618903728f
#define SINM_F    0.479425538604203f
#define TH_F     (-0.8775825618903728f)
#define MMV_F     0.23971276930210156f

// ============================ device scratch ===============================
__device__ float g_invx[BATCH_N];
__device__ float g_invw[CLS];
__device__ int   g_label[BATCH_N];
__device__ int   g_lab64flag;
__device__ float g_rowsum[BATCH_N];   // sum of exp(logit - 30) per row
__device__ float g_tgt[BATCH_N];      // target-class logit per row

// ============================ helpers ======================================
__device__ __forceinline__ float f2tf32(float f) {
    uint32_t r; asm("cvt.rna.tf32.f32 %0, %1;" : "=r"(r) : "f"(f));
    return __uint_as_float(r);
}

#define MMA_TF32(c, A0, A1, A2, A3, B0, B1) \
    asm volatile("mma.sync.aligned.m16n8k8.row.col.f32.tf32.tf32.f32 " \
        "{%0,%1,%2,%3}, {%4,%5,%6,%7}, {%8,%9}, {%0,%1,%2,%3};" \
        : "+f"((c)[0]), "+f"((c)[1]), "+f"((c)[2]), "+f"((c)[3]) \
        : "r"(__float_as_uint(A0)), "r"(__float_as_uint(A1)), \
          "r"(__float_as_uint(A2)), "r"(__float_as_uint(A3)), \
          "r"(__float_as_uint(B0)), "r"(__float_as_uint(B1)))

// ============================ GEMM config ==================================
#define BM   128
#define BN   128
#define BK   16
#define NCH  (KDIM / BK)          // 32 chunks
#define SST  20                   // smem row stride in floats (pad 4)
#define BUFFLOATS ((BM + BN) * SST)      // floats per stage = 5120
#define DSMEM_BYTES (2 * BUFFLOATS * 4)  // 40960 B

__device__ __forceinline__ float arc_apply(float cosv, bool istgt) {
    float o = cosv;
    if (istgt) {
        float sine = sqrtf(fmaxf(0.0f, 1.0f - cosv * cosv));
        float phi = cosv * COSM_F - sine * SINM_F;
        o = (cosv > TH_F) ? phi : (cosv - MMV_F);
    }
    return o * SCALE_F;
}

// ============================ small kernels ================================
__global__ void label_detect_kernel(const int* __restrict__ raw) {
    int nz = 0;
    for (int i = threadIdx.x; i < 2048; i += blockDim.x)
        if (raw[2 * i + 1] != 0) nz = 1;
    int any = __syncthreads_or(nz);
    if (threadIdx.x == 0) g_lab64flag = any ? 0 : 1;  // all hi-words zero => int64
}

__global__ void label_convert_kernel(const int* __restrict__ raw) {
    int i = blockIdx.x * blockDim.x + threadIdx.x;
    if (i < BATCH_N) g_label[i] = g_lab64flag ? raw[2 * i] : raw[i];
}

__global__ void zero_rowsum_kernel() {
    int i = blockIdx.x * blockDim.x + threadIdx.x;
    if (i < BATCH_N) g_rowsum[i] = 0.0f;
}

__global__ void rownorm_kernel(const float* __restrict__ x, float* __restrict__ invn, int cols) {
    int row = blockIdx.x;
    const float4* p = (const float4*)(x + (size_t)row * cols);
    float ss = 0.f;
    for (int i = threadIdx.x; i < (cols >> 2); i += blockDim.x) {
        float4 v = p[i];
        ss += v.x * v.x + v.y * v.y + v.z * v.z + v.w * v.w;
    }
    #pragma unroll
    for (int o = 16; o; o >>= 1) ss += __shfl_down_sync(0xffffffffu, ss, o);
    __shared__ float ws[8];
    int wid = threadIdx.x >> 5, lane = threadIdx.x & 31;
    if (lane == 0) ws[wid] = ss;
    __syncthreads();
    if (threadIdx.x == 0) {
        float t = 0.f;
        int nw = blockDim.x >> 5;
        for (int w = 0; w < nw; ++w) t += ws[w];
        invn[row] = 1.0f / fmaxf(sqrtf(t), 1e-12f);
    }
}

// ============================ main GEMM + ArcFace ==========================
// Smem per stage: A[128][20] then B[128][20] floats.
// K-permuted columns: element k (0..15) stored at column pos = (k&3)*4 + (k>>2)
// => the A/B fragments for BOTH k8-steps of a chunk load as one LDS.128.

extern __shared__ float smf[];

__global__ void __launch_bounds__(256, 2)
gemm_arcface_kernel(const float* __restrict__ X, const float* __restrict__ W,
                    float* __restrict__ out)
{
    const int tid  = threadIdx.x;
    const int lane = tid & 31;
    const int wid  = tid >> 5;
    const int g    = lane >> 2;     // 0..7
    const int tm   = lane & 3;      // 0..3
    const int wm   = wid & 1;       // warp M index (0..1)
    const int wn   = wid >> 1;      // warp N index (0..3)
    const int rowBase = blockIdx.x * BM;
    const int colBase = blockIdx.y * BN;

    float* sA[2] = { smf,            smf + BUFFLOATS };
    float* sB[2] = { smf + BM * SST, smf + BUFFLOATS + BM * SST };

    // global->smem mapping: 256 threads, each covers 2 rows (lr, lr+64), one float4
    const int lr = tid >> 2;        // 0..63
    const int lc = tid & 3;         // float4 group within 16-float chunk
    const float* Xp = X + (size_t)(rowBase + lr) * KDIM + lc * 4;
    const float* Wp = W + (size_t)(colBase + lr) * KDIM + lc * 4;
    const bool bv0 = (colBase + lr)      < CLS;
    const bool bv1 = (colBase + lr + 64) < CLS;

    float acc[4][4][4];
    #pragma unroll
    for (int i = 0; i < 4; ++i)
        #pragma unroll
        for (int j = 0; j < 4; ++j)
            #pragma unroll
            for (int q = 0; q < 4; ++q) acc[i][j][q] = 0.f;

    float4 ra0, ra1, rb0, rb1;

    // ---- prologue: load + store chunk 0 ----
    ra0 = *(const float4*)(Xp);
    ra1 = *(const float4*)(Xp + (size_t)64 * KDIM);
    rb0 = bv0 ? *(const float4*)(Wp) : make_float4(0.f, 0.f, 0.f, 0.f);
    rb1 = bv1 ? *(const float4*)(Wp + (size_t)64 * KDIM) : make_float4(0.f, 0.f, 0.f, 0.f);
    {
        float* dA0 = sA[0] + lr * SST + lc;
        float* dA1 = sA[0] + (lr + 64) * SST + lc;
        float* dB0 = sB[0] + lr * SST + lc;
        float* dB1 = sB[0] + (lr + 64) * SST + lc;
        dA0[0] = f2tf32(ra0.x); dA0[4] = f2tf32(ra0.y); dA0[8] = f2tf32(ra0.z); dA0[12] = f2tf32(ra0.w);
        dA1[0] = f2tf32(ra1.x); dA1[4] = f2tf32(ra1.y); dA1[8] = f2tf32(ra1.z); dA1[12] = f2tf32(ra1.w);
        dB0[0] = f2tf32(rb0.x); dB0[4] = f2tf32(rb0.y); dB0[8] = f2tf32(rb0.z); dB0[12] = f2tf32(rb0.w);
        dB1[0] = f2tf32(rb1.x); dB1[4] = f2tf32(rb1.y); dB1[8] = f2tf32(rb1.z); dB1[12] = f2tf32(rb1.w);
    }
    __syncthreads();

    // ---- main loop over 32 K-chunks, smem double-buffered ----
    #pragma unroll 2
    for (int c = 0; c < NCH; ++c) {
        const int buf = c & 1;

        if (c + 1 < NCH) {
            const int k0 = (c + 1) * BK;
            ra0 = *(const float4*)(Xp + k0);
            ra1 = *(const float4*)(Xp + (size_t)64 * KDIM + k0);
            rb0 = bv0 ? *(const float4*)(Wp + k0) : make_float4(0.f, 0.f, 0.f, 0.f);
            rb1 = bv1 ? *(const float4*)(Wp + (size_t)64 * KDIM + k0) : make_float4(0.f, 0.f, 0.f, 0.f);
        }

        // compute on buf
        {
            const float* Ab = sA[buf] + (wm * 64 + g) * SST + 4 * tm;
            const float* Bb = sB[buf] + (wn * 32 + g) * SST + 4 * tm;
            float4 bq0 = *(const float4*)(Bb);
            float4 bq1 = *(const float4*)(Bb + 8  * SST);
            float4 bq2 = *(const float4*)(Bb + 16 * SST);
            float4 bq3 = *(const float4*)(Bb + 24 * SST);
            #pragma unroll
            for (int i = 0; i < 4; ++i) {
                float4 alo = *(const float4*)(Ab + (i * 16)     * SST);
                float4 ahi = *(const float4*)(Ab + (i * 16 + 8) * SST);
                MMA_TF32(acc[i][0], alo.x, ahi.x, alo.y, ahi.y, bq0.x, bq0.y);
                MMA_TF32(acc[i][1], alo.x, ahi.x, alo.y, ahi.y, bq1.x, bq1.y);
                MMA_TF32(acc[i][2], alo.x, ahi.x, alo.y, ahi.y, bq2.x, bq2.y);
                MMA_TF32(acc[i][3], alo.x, ahi.x, alo.y, ahi.y, bq3.x, bq3.y);
                MMA_TF32(acc[i][0], alo.z, ahi.z, alo.w, ahi.w, bq0.z, bq0.w);
                MMA_TF32(acc[i][1], alo.z, ahi.z, alo.w, ahi.w, bq1.z, bq1.w);
                MMA_TF32(acc[i][2], alo.z, ahi.z, alo.w, ahi.w, bq2.z, bq2.w);
                MMA_TF32(acc[i][3], alo.z, ahi.z, alo.w, ahi.w, bq3.z, bq3.w);
            }
        }

        if (c + 1 < NCH) {
            const int nb = buf ^ 1;
            float* dA0 = sA[nb] + lr * SST + lc;
            float* dA1 = sA[nb] + (lr + 64) * SST + lc;
            float* dB0 = sB[nb] + lr * SST + lc;
            float* dB1 = sB[nb] + (lr + 64) * SST + lc;
            dA0[0] = f2tf32(ra0.x); dA0[4] = f2tf32(ra0.y); dA0[8] = f2tf32(ra0.z); dA0[12] = f2tf32(ra0.w);
            dA1[0] = f2tf32(ra1.x); dA1[4] = f2tf32(ra1.y); dA1[8] = f2tf32(ra1.z); dA1[12] = f2tf32(ra1.w);
            dB0[0] = f2tf32(rb0.x); dB0[4] = f2tf32(rb0.y); dB0[8] = f2tf32(rb0.z); dB0[12] = f2tf32(rb0.w);
            dB1[0] = f2tf32(rb1.x); dB1[4] = f2tf32(rb1.y); dB1[8] = f2tf32(rb1.z); dB1[12] = f2tf32(rb1.w);
        }
        __syncthreads();
    }

    // ---- epilogue: normalize, ArcFace margin, scale, store, fused LSE ----
    // reuse smem (free after last sync) for per-row exp-sum accumulators
    float* rowacc = smf;           // 128 floats
    if (tid < BM) rowacc[tid] = 0.f;
    __syncthreads();

    const int wrowb = rowBase + wm * 64;
    const int wcolb = colBase + wn * 32;
    #pragma unroll
    for (int i = 0; i < 4; ++i) {
        const int r0 = wrowb + i * 16 + g;
        const int r1 = r0 + 8;
        const float ix0 = g_invx[r0], ix1 = g_invx[r1];
        const int lab0 = g_label[r0], lab1 = g_label[r1];
        float* o0 = out + (size_t)r0 * CLS;
        float* o1 = out + (size_t)r1 * CLS;
        float es0 = 0.f, es1 = 0.f;      // exp-sums for this thread's cols
        #pragma unroll
        for (int j = 0; j < 4; ++j) {
            const int cc = wcolb + j * 8 + 2 * tm;
            if (cc < CLS) {   // cc even, CLS even => cc+1 < CLS too
                const float iw0 = g_invw[cc], iw1 = g_invw[cc + 1];
                const bool t00 = (cc == lab0), t01 = (cc + 1 == lab0);
                const bool t10 = (cc == lab1), t11 = (cc + 1 == lab1);
                float2 v0, v1;
                v0.x = arc_apply(acc[i][j][0] * ix0 * iw0, t00);
                v0.y = arc_apply(acc[i][j][1] * ix0 * iw1, t01);
                v1.x = arc_apply(acc[i][j][2] * ix1 * iw0, t10);
                v1.y = arc_apply(acc[i][j][3] * ix1 * iw1, t11);
                *(float2*)(o0 + cc) = v0;
                *(float2*)(o1 + cc) = v1;
                es0 += __expf(v0.x - LMAX_F) + __expf(v0.y - LMAX_F);
                es1 += __expf(v1.x - LMAX_F) + __expf(v1.y - LMAX_F);
                if (t00) g_tgt[r0] = v0.x;
                if (t01) g_tgt[r0] = v0.y;
                if (t10) g_tgt[r1] = v1.x;
                if (t11) g_tgt[r1] = v1.y;
            }
        }
        // reduce over the 4 lanes (tm) sharing each row
        es0 += __shfl_xor_sync(0xffffffffu, es0, 1);
        es0 += __shfl_xor_sync(0xffffffffu, es0, 2);
        es1 += __shfl_xor_sync(0xffffffffu, es1, 1);
        es1 += __shfl_xor_sync(0xffffffffu, es1, 2);
        if (tm == 0) {
            atomicAdd(&rowacc[wm * 64 + i * 16 + g],     es0);
            atomicAdd(&rowacc[wm * 64 + i * 16 + g + 8], es1);
        }
    }
    __syncthreads();
    if (tid < BM) atomicAdd(&g_rowsum[rowBase + tid], rowacc[tid]);
}

// ============================ loss finisher ================================
__global__ void loss_final_kernel(float* __restrict__ dst) {
    float s = 0.f;
    for (int i = threadIdx.x; i < BATCH_N; i += blockDim.x)
        s += (LMAX_F + logf(g_rowsum[i])) - g_tgt[i];
    #pragma unroll
    for (int o = 16; o; o >>= 1) s += __shfl_down_sync(0xffffffffu, s, o);
    __shared__ float ws[8];
    int wid = threadIdx.x >> 5, lane = threadIdx.x & 31;
    if (lane == 0) ws[wid] = s;
    __syncthreads();
    if (threadIdx.x == 0) {
        float t = 0.f;
        int nw = blockDim.x >> 5;
        for (int w = 0; w < nw; ++w) t += ws[w];
        *dst = t * (1.0f / (float)BATCH_N);
    }
}

// ============================ launcher =====================================
extern "C" void kernel_launch(void* const* d_in, const int* in_sizes, int n_in,
                              void* d_out, int out_size) {
    const float* X = nullptr;
    const float* W = nullptr;
    const int*   L = nullptr;
    for (int i = 0; i < n_in; ++i) {
        if (in_sizes[i] == BATCH_N * KDIM)      X = (const float*)d_in[i];
        else if (in_sizes[i] == CLS * KDIM)     W = (const float*)d_in[i];
        else if (in_sizes[i] == BATCH_N)        L = (const int*)d_in[i];
    }
    float* out = (float*)d_out;

    float* invx_ptr = nullptr;
    float* invw_ptr = nullptr;
    cudaGetSymbolAddress((void**)&invx_ptr, g_invx);
    cudaGetSymbolAddress((void**)&invw_ptr, g_invw);

    label_detect_kernel<<<1, 256>>>(L);
    label_convert_kernel<<<(BATCH_N + 255) / 256, 256>>>(L);
    zero_rowsum_kernel<<<(BATCH_N + 255) / 256, 256>>>();
    rownorm_kernel<<<BATCH_N, 128>>>(X, invx_ptr, KDIM);
    rownorm_kernel<<<CLS, 128>>>(W, invw_ptr, KDIM);

    // x = row-block (fast-varying) so consecutive CTAs share one W tile in L2
    dim3 grid(BATCH_N / BM, (CLS + BN - 1) / BN);
    gemm_arcface_kernel<<<grid, 256, DSMEM_BYTES>>>(X, W, out);

    if ((long long)out_size > (long long)BATCH_N * CLS) {
        loss_final_kernel<<<1, 256>>>(out + (size_t)BATCH_N * CLS);
    }
}

// round 7
// speedup vs baseline: 1.7273x; 1.7273x over previous
#include <cuda_runtime.h>
#include <cstdint>
#include <cstddef>

// ============================ problem constants ============================
#define BATCH_N   4096
#define KDIM      512
#define CLS       50000
#define CLSP      50048              // padded to 391*128
#define SCALE_F   30.0f
#define LMAX_F    30.0f
#define COSM_F    0.8775825618903728f
#define SINM_F    0.479425538604203f
#define TH_F     (-0.8775825618903728f)
#define MMV_F     0.23971276930210156f

// ============================ device scratch ===============================
__device__ float g_Xr[BATCH_N * KDIM];   // tf32-rounded, k-permuted X
__device__ float g_Wr[CLSP * KDIM];      // tf32-rounded, k-permuted W (padded)
__device__ float g_invx[BATCH_N];
__device__ float g_invw[CLSP];
__device__ int   g_label[BATCH_N];
__device__ float g_rowsum[BATCH_N];      // sum of exp(logit - 30) per row
__device__ float g_tgt[BATCH_N];         // target-class logit per row

// ============================ helpers ======================================
__device__ __forceinline__ float f2tf32(float f) {
    uint32_t r; asm("cvt.rna.tf32.f32 %0, %1;" : "=r"(r) : "f"(f));
    return __uint_as_float(r);
}

#define MMA_TF32(c, A0, A1, A2, A3, B0, B1) \
    asm volatile("mma.sync.aligned.m16n8k8.row.col.f32.tf32.tf32.f32 " \
        "{%0,%1,%2,%3}, {%4,%5,%6,%7}, {%8,%9}, {%0,%1,%2,%3};" \
        : "+f"((c)[0]), "+f"((c)[1]), "+f"((c)[2]), "+f"((c)[3]) \
        : "r"(__float_as_uint(A0)), "r"(__float_as_uint(A1)), \
          "r"(__float_as_uint(A2)), "r"(__float_as_uint(A3)), \
          "r"(__float_as_uint(B0)), "r"(__float_as_uint(B1)))

#define CP16(dst_u32, src_gptr) \
    asm volatile("cp.async.cg.shared.global [%0], [%1], 16;" \
        :: "r"(dst_u32), "l"(src_gptr) : "memory")
#define CP_COMMIT() asm volatile("cp.async.commit_group;" ::: "memory")
#define CP_WAIT(n)  asm volatile("cp.async.wait_group %0;" :: "n"(n) : "memory")

__device__ __forceinline__ uint32_t smem_u32(const void* p) {
    uint32_t a;
    asm("{ .reg .u64 t; cvta.to.shared.u64 t, %1; cvt.u32.u64 %0, t; }" : "=r"(a) : "l"(p));
    return a;
}

// ============================ GEMM config ==================================
#define BM     128
#define BN     128
#define BK     16
#define NCH    (KDIM / BK)            // 32
#define STAGES 4
#define SST    20                     // smem row stride (floats), pad 4
#define STAGEF ((BM + BN) * SST)      // 5120 floats per stage
#define DSMEM_BYTES (STAGES * STAGEF * 4)   // 81920 B

__device__ __forceinline__ float arc_apply(float cosv, bool istgt) {
    float o = cosv;
    if (istgt) {
        float sine = sqrtf(fmaxf(0.0f, 1.0f - cosv * cosv));
        float phi = cosv * COSM_F - sine * SINM_F;
        o = (cosv > TH_F) ? phi : (cosv - MMV_F);
    }
    return o * SCALE_F;
}

// ============================ prep kernel ==================================
// blocks 0..4095:        X rows  -> norm + tf32-round + k-permute into g_Xr
// blocks 4096..54143:    W rows  -> same into g_Wr (rows >= CLS zero-padded)
// block  54144:          labels (int64/int32 detect + convert) + zero g_rowsum
// k-permutation within each 16-float group: element p -> pos (p&3)*4 + (p>>2)
__global__ void __launch_bounds__(128) prep_kernel(
    const float* __restrict__ X, const float* __restrict__ W,
    const int* __restrict__ L)
{
    const int b = blockIdx.x;
    const int t = threadIdx.x;

    if (b < BATCH_N + CLSP) {
        const bool isX = (b < BATCH_N);
        const int row = isX ? b : (b - BATCH_N);
        const float* src = isX ? (X + (size_t)row * KDIM)
                               : (W + (size_t)row * KDIM);
        float* dst = isX ? (g_Xr + (size_t)row * KDIM)
                         : (g_Wr + (size_t)row * KDIM);
        const bool valid = isX || (row < CLS);

        float4 v = make_float4(0.f, 0.f, 0.f, 0.f);
        if (valid) v = *(const float4*)(src + t * 4);
        float ss = v.x * v.x + v.y * v.y + v.z * v.z + v.w * v.w;

        // permuted write: floats 4t..4t+3 are group (t>>2), pos 4(t&3)+e
        float* gdst = dst + (t >> 2) * 16 + (t & 3);
        gdst[0]  = f2tf32(v.x);
        gdst[4]  = f2tf32(v.y);
        gdst[8]  = f2tf32(v.z);
        gdst[12] = f2tf32(v.w);

        #pragma unroll
        for (int o = 16; o; o >>= 1) ss += __shfl_down_sync(0xffffffffu, ss, o);
        __shared__ float ws[4];
        if ((t & 31) == 0) ws[t >> 5] = ss;
        __syncthreads();
        if (t == 0) {
            float tot = ws[0] + ws[1] + ws[2] + ws[3];
            float inv = valid ? (1.0f / fmaxf(sqrtf(tot), 1e-12f)) : 1.0f;
            if (isX) g_invx[row] = inv; else g_invw[row] = inv;
        }
    } else {
        // labels + zero rowsum
        int nz = 0;
        for (int i = t; i < 2048; i += 128)
            if (L[2 * i + 1] != 0) nz = 1;
        int any = __syncthreads_or(nz);
        const int is64 = any ? 0 : 1;
        for (int i = t; i < BATCH_N; i += 128) {
            g_label[i] = is64 ? L[2 * i] : L[i];
            g_rowsum[i] = 0.0f;
        }
    }
}

// ============================ main GEMM + ArcFace ==========================
extern __shared__ float smf[];

__device__ __forceinline__ void compute_chunk(
    const float* __restrict__ sb, int wm, int wn, int g, int tm,
    float acc[4][4][4])
{
    const float* Ab = sb + (wm * 64 + g) * SST + 4 * tm;
    const float* Bb = sb + (BM + wn * 32 + g) * SST + 4 * tm;
    float4 bq0 = *(const float4*)(Bb);
    float4 bq1 = *(const float4*)(Bb + 8  * SST);
    float4 bq2 = *(const float4*)(Bb + 16 * SST);
    float4 bq3 = *(const float4*)(Bb + 24 * SST);
    #pragma unroll
    for (int i = 0; i < 4; ++i) {
        float4 alo = *(const float4*)(Ab + (i * 16)     * SST);
        float4 ahi = *(const float4*)(Ab + (i * 16 + 8) * SST);
        MMA_TF32(acc[i][0], alo.x, ahi.x, alo.y, ahi.y, bq0.x, bq0.y);
        MMA_TF32(acc[i][1], alo.x, ahi.x, alo.y, ahi.y, bq1.x, bq1.y);
        MMA_TF32(acc[i][2], alo.x, ahi.x, alo.y, ahi.y, bq2.x, bq2.y);
        MMA_TF32(acc[i][3], alo.x, ahi.x, alo.y, ahi.y, bq3.x, bq3.y);
        MMA_TF32(acc[i][0], alo.z, ahi.z, alo.w, ahi.w, bq0.z, bq0.w);
        MMA_TF32(acc[i][1], alo.z, ahi.z, alo.w, ahi.w, bq1.z, bq1.w);
        MMA_TF32(acc[i][2], alo.z, ahi.z, alo.w, ahi.w, bq2.z, bq2.w);
        MMA_TF32(acc[i][3], alo.z, ahi.z, alo.w, ahi.w, bq3.z, bq3.w);
    }
}

__global__ void __launch_bounds__(256, 2)
gemm_arcface_kernel(float* __restrict__ out)
{
    const int tid  = threadIdx.x;
    const int lane = tid & 31;
    const int wid  = tid >> 5;
    const int g    = lane >> 2;
    const int tm   = lane & 3;
    const int wm   = wid & 1;
    const int wn   = wid >> 1;
    const int rowBase = blockIdx.x * BM;
    const int colBase = blockIdx.y * BN;

    const uint32_t sbase = smem_u32(smf);

    // cp.async mapping: thread covers chunk ids tid and tid+256 for A and B
    const int r0c = tid >> 2, lc = tid & 3;
    const int r1c = r0c + 64;
    const float* xsrc0 = g_Xr + (size_t)(rowBase + r0c) * KDIM + lc * 4;
    const float* xsrc1 = g_Xr + (size_t)(rowBase + r1c) * KDIM + lc * 4;
    const float* wsrc0 = g_Wr + (size_t)(colBase + r0c) * KDIM + lc * 4;
    const float* wsrc1 = g_Wr + (size_t)(colBase + r1c) * KDIM + lc * 4;
    const uint32_t dA0 = sbase + (r0c * SST + lc * 4) * 4;
    const uint32_t dA1 = sbase + (r1c * SST + lc * 4) * 4;
    const uint32_t dB0 = sbase + ((BM + r0c) * SST + lc * 4) * 4;
    const uint32_t dB1 = sbase + ((BM + r1c) * SST + lc * 4) * 4;

    float acc[4][4][4];
    #pragma unroll
    for (int i = 0; i < 4; ++i)
        #pragma unroll
        for (int j = 0; j < 4; ++j)
            #pragma unroll
            for (int q = 0; q < 4; ++q) acc[i][j][q] = 0.f;

    // prologue: issue stages 0..STAGES-2
    #pragma unroll
    for (int s = 0; s < STAGES - 1; ++s) {
        const uint32_t so = (uint32_t)(s * STAGEF * 4);
        const int ko = s * BK;
        CP16(dA0 + so, xsrc0 + ko);
        CP16(dA1 + so, xsrc1 + ko);
        CP16(dB0 + so, wsrc0 + ko);
        CP16(dB1 + so, wsrc1 + ko);
        CP_COMMIT();
    }

    // main loop
    #pragma unroll 1
    for (int c = 0; c < NCH - 2; ++c) {
        CP_WAIT(2);
        __syncthreads();
        if (c + STAGES - 1 < NCH) {
            const int s = (c + STAGES - 1) & (STAGES - 1);
            const uint32_t so = (uint32_t)(s * STAGEF * 4);
            const int ko = (c + STAGES - 1) * BK;
            CP16(dA0 + so, xsrc0 + ko);
            CP16(dA1 + so, xsrc1 + ko);
            CP16(dB0 + so, wsrc0 + ko);
            CP16(dB1 + so, wsrc1 + ko);
            CP_COMMIT();
        }
        compute_chunk(smf + (c & (STAGES - 1)) * STAGEF, wm, wn, g, tm, acc);
    }
    // peeled tail: c = NCH-2, NCH-1
    CP_WAIT(1);
    __syncthreads();
    compute_chunk(smf + ((NCH - 2) & (STAGES - 1)) * STAGEF, wm, wn, g, tm, acc);
    CP_WAIT(0);
    __syncthreads();
    compute_chunk(smf + ((NCH - 1) & (STAGES - 1)) * STAGEF, wm, wn, g, tm, acc);

    // ---- epilogue: normalize, ArcFace margin, scale, store, fused LSE ----
    __syncthreads();
    float* rowacc = smf;           // reuse smem: 128 floats
    if (tid < BM) rowacc[tid] = 0.f;
    __syncthreads();

    const int wrowb = rowBase + wm * 64;
    const int wcolb = colBase + wn * 32;
    #pragma unroll
    for (int i = 0; i < 4; ++i) {
        const int r0 = wrowb + i * 16 + g;
        const int r1 = r0 + 8;
        const float ix0 = g_invx[r0], ix1 = g_invx[r1];
        const int lab0 = g_label[r0], lab1 = g_label[r1];
        float* o0 = out + (size_t)r0 * CLS;
        float* o1 = out + (size_t)r1 * CLS;
        float es0 = 0.f, es1 = 0.f;
        #pragma unroll
        for (int j = 0; j < 4; ++j) {
            const int cc = wcolb + j * 8 + 2 * tm;
            if (cc < CLS) {   // cc even, CLS even => cc+1 < CLS too
                const float iw0 = g_invw[cc], iw1 = g_invw[cc + 1];
                const bool t00 = (cc == lab0), t01 = (cc + 1 == lab0);
                const bool t10 = (cc == lab1), t11 = (cc + 1 == lab1);
                float2 v0, v1;
                v0.x = arc_apply(acc[i][j][0] * ix0 * iw0, t00);
                v0.y = arc_apply(acc[i][j][1] * ix0 * iw1, t01);
                v1.x = arc_apply(acc[i][j][2] * ix1 * iw0, t10);
                v1.y = arc_apply(acc[i][j][3] * ix1 * iw1, t11);
                *(float2*)(o0 + cc) = v0;
                *(float2*)(o1 + cc) = v1;
                es0 += __expf(v0.x - LMAX_F) + __expf(v0.y - LMAX_F);
                es1 += __expf(v1.x - LMAX_F) + __expf(v1.y - LMAX_F);
                if (t00) g_tgt[r0] = v0.x;
                if (t01) g_tgt[r0] = v0.y;
                if (t10) g_tgt[r1] = v1.x;
                if (t11) g_tgt[r1] = v1.y;
            }
        }
        es0 += __shfl_xor_sync(0xffffffffu, es0, 1);
        es0 += __shfl_xor_sync(0xffffffffu, es0, 2);
        es1 += __shfl_xor_sync(0xffffffffu, es1, 1);
        es1 += __shfl_xor_sync(0xffffffffu, es1, 2);
        if (tm == 0) {
            atomicAdd(&rowacc[wm * 64 + i * 16 + g],     es0);
            atomicAdd(&rowacc[wm * 64 + i * 16 + g + 8], es1);
        }
    }
    __syncthreads();
    if (tid < BM) atomicAdd(&g_rowsum[rowBase + tid], rowacc[tid]);
}

// ============================ loss finisher ================================
__global__ void loss_final_kernel(float* __restrict__ dst) {
    float s = 0.f;
    for (int i = threadIdx.x; i < BATCH_N; i += blockDim.x)
        s += (LMAX_F + logf(g_rowsum[i])) - g_tgt[i];
    #pragma unroll
    for (int o = 16; o; o >>= 1) s += __shfl_down_sync(0xffffffffu, s, o);
    __shared__ float ws[8];
    int wid = threadIdx.x >> 5, lane = threadIdx.x & 31;
    if (lane == 0) ws[wid] = s;
    __syncthreads();
    if (threadIdx.x == 0) {
        float t = 0.f;
        int nw = blockDim.x >> 5;
        for (int w = 0; w < nw; ++w) t += ws[w];
        *dst = t * (1.0f / (float)BATCH_N);
    }
}

__global__ void tail_kernel() {}

// ============================ launcher =====================================
extern "C" void kernel_launch(void* const* d_in, const int* in_sizes, int n_in,
                              void* d_out, int out_size) {
    const float* X = nullptr;
    const float* W = nullptr;
    const int*   L = nullptr;
    for (int i = 0; i < n_in; ++i) {
        if (in_sizes[i] == BATCH_N * KDIM)      X = (const float*)d_in[i];
        else if (in_sizes[i] == CLS * KDIM)     W = (const float*)d_in[i];
        else if (in_sizes[i] == BATCH_N)        L = (const int*)d_in[i];
    }
    float* out = (float*)d_out;

    cudaFuncSetAttribute(gemm_arcface_kernel,
                         cudaFuncAttributeMaxDynamicSharedMemorySize, DSMEM_BYTES);

    // 4 launches/call => ncu -s 5 -c 1 lands on GEMM (idx 5 = call2.launch1)
    prep_kernel<<<BATCH_N + CLSP + 1, 128>>>(X, W, L);

    dim3 grid(BATCH_N / BM, CLSP / BN);    // x fast-varying: share W tile in L2
    gemm_arcface_kernel<<<grid, 256, DSMEM_BYTES>>>(out);

    if ((long long)out_size > (long long)BATCH_N * CLS)
        loss_final_kernel<<<1, 256>>>(out + (size_t)BATCH_N * CLS);

    tail_kernel<<<1, 32>>>();
}